// round 5
// baseline (speedup 1.0000x reference)
#include <cuda_runtime.h>
#include <cstdint>

#define BATCH 4
#define NPTS  8192
#define KNN   16
#define CIN   64
#define CO    64
#define F3    192
#define CS    20
#define NQ    (BATCH * NPTS)
#define CHUNKS 4
#define CPC   (NPTS / CHUNKS)     // 2048
#define PAIRS (CPC / 2)           // 1024
#define QPB   256                 // queries per knn block (128 threads x 2)

typedef unsigned long long ull;
typedef unsigned int uint;

__device__ int   g_idx[NQ * KNN];
__device__ float g_feat3[(size_t)NQ * F3];
__device__ float g_pd[CHUNKS * NQ * KNN];
__device__ int   g_pi[CHUNKS * NQ * KNN];
__device__ float g_WgT[CO * CO];   // [c][o] = (w_gamma2 @ w_gamma1)^T
__device__ float g_WtT[3 * CO];    // [c3][o] = (w_theta2 @ w_theta1)^T

// ---------------------------------------------------------------------------
// packed f32x2 helpers
// ---------------------------------------------------------------------------
__device__ __forceinline__ ull pack2(float f) {
    ull r; uint u = __float_as_uint(f);
    asm("mov.b64 %0, {%1, %1};" : "=l"(r) : "r"(u));
    return r;
}
__device__ __forceinline__ ull packpair(float lo, float hi) {
    ull r;
    asm("mov.b64 %0, {%1, %2};" : "=l"(r) : "r"(__float_as_uint(lo)), "r"(__float_as_uint(hi)));
    return r;
}
__device__ __forceinline__ void fma2(ull& acc, ull a, ull b) {
    asm("fma.rn.f32x2 %0, %1, %2, %0;" : "+l"(acc) : "l"(a), "l"(b));
}
__device__ __forceinline__ float f2lo(ull v) { return __uint_as_float((uint)v); }
__device__ __forceinline__ float f2hi(ull v) { return __uint_as_float((uint)(v >> 32)); }

// ---------------------------------------------------------------------------
__device__ __forceinline__ void insert16(float d, int id, float bd[KNN], int bi[KNN]) {
#pragma unroll
    for (int t = 0; t < KNN; ++t) {
        bool p = d < bd[t];
        float td = bd[t]; int ti = bi[t];
        bd[t] = p ? d : bd[t];
        bi[t] = p ? id : bi[t];
        d  = p ? td : d;
        id = p ? ti : id;
    }
}

// ---------------------------------------------------------------------------
// Kernel 1: partial KNN. 2 queries/thread, f32x2 pair-packed candidates,
// geometric-window deferred insertion. key = |m|^2 - 2 q.m
// ---------------------------------------------------------------------------
__global__ void __launch_bounds__(128) knn_part(const float* __restrict__ coords) {
    __shared__ ull   s_pt[PAIRS * 4];      // 32KB: per pair {x2,y2,z2,w2}
    __shared__ float s_bd[KNN * 256];      // 16KB: deferral buffers (2 q-slots)
    __shared__ int   s_bi[KNN * 256];      // 16KB

    const int tid = threadIdx.x;
    const int b = blockIdx.y;
    const int chunk = blockIdx.z;
    const int qa = blockIdx.x * QPB + tid;
    const int qb = qa + 128;
    const float* cb = coords + (size_t)b * 3 * NPTS;
    const int cbase = chunk * CPC;

    // fill packed candidate tile
    for (int jp = tid; jp < PAIRS; jp += 128) {
        float2 x = *(const float2*)(cb + cbase + 2 * jp);
        float2 y = *(const float2*)(cb + NPTS + cbase + 2 * jp);
        float2 z = *(const float2*)(cb + 2 * NPTS + cbase + 2 * jp);
        float w0 = fmaf(z.x, z.x, fmaf(y.x, y.x, x.x * x.x));
        float w1 = fmaf(z.y, z.y, fmaf(y.y, y.y, x.y * x.y));
        ull* p = s_pt + (size_t)jp * 4;
        p[0] = packpair(x.x, x.y);
        p[1] = packpair(y.x, y.y);
        p[2] = packpair(z.x, z.y);
        p[3] = packpair(w0, w1);
    }

    const ull nxa = pack2(-2.f * cb[qa]);
    const ull nya = pack2(-2.f * cb[NPTS + qa]);
    const ull nza = pack2(-2.f * cb[2 * NPTS + qa]);
    const ull nxb = pack2(-2.f * cb[qb]);
    const ull nyb = pack2(-2.f * cb[NPTS + qb]);
    const ull nzb = pack2(-2.f * cb[2 * NPTS + qb]);

    float bda[KNN], bdb[KNN];
    int   bia[KNN], bib[KNN];
#pragma unroll
    for (int j = 0; j < KNN; ++j) {
        bda[j] = 3.4e38f; bia[j] = 0;
        bdb[j] = 3.4e38f; bib[j] = 0;
    }
    float ta = 3.4e38f, tb = 3.4e38f;
    int ca = 0, cbn = 0;
    __syncthreads();

    // geometric windows over pair index: (0,8),(8,16),(16,32)...(512,1024)
    for (int w = 0; w < 8; ++w) {
        const int j0 = (w == 0) ? 0 : (4 << w);
        const int j1 = 8 << w;
#pragma unroll 2
        for (int jp = j0; jp < j1; ++jp) {
            ulonglong2 p01 = *(const ulonglong2*)(s_pt + (size_t)jp * 4);
            ulonglong2 p23 = *(const ulonglong2*)(s_pt + (size_t)jp * 4 + 2);
            const int i0 = cbase + 2 * jp;
            // query a
            {
                ull d2 = p23.y;
                fma2(d2, nza, p23.x);
                fma2(d2, nya, p01.y);
                fma2(d2, nxa, p01.x);
                float d0 = f2lo(d2), d1 = f2hi(d2);
                if (d0 < ta || d1 < ta) {
                    if (d0 < ta) {
                        if (ca < KNN) { s_bd[ca * 256 + tid] = d0; s_bi[ca * 256 + tid] = i0; ca++; }
                        else { insert16(d0, i0, bda, bia); ta = bda[KNN - 1]; }
                    }
                    if (d1 < ta) {
                        if (ca < KNN) { s_bd[ca * 256 + tid] = d1; s_bi[ca * 256 + tid] = i0 + 1; ca++; }
                        else { insert16(d1, i0 + 1, bda, bia); ta = bda[KNN - 1]; }
                    }
                }
            }
            // query b
            {
                ull d2 = p23.y;
                fma2(d2, nzb, p23.x);
                fma2(d2, nyb, p01.y);
                fma2(d2, nxb, p01.x);
                float d0 = f2lo(d2), d1 = f2hi(d2);
                if (d0 < tb || d1 < tb) {
                    if (d0 < tb) {
                        if (cbn < KNN) { s_bd[cbn * 256 + 128 + tid] = d0; s_bi[cbn * 256 + 128 + tid] = i0; cbn++; }
                        else { insert16(d0, i0, bdb, bib); tb = bdb[KNN - 1]; }
                    }
                    if (d1 < tb) {
                        if (cbn < KNN) { s_bd[cbn * 256 + 128 + tid] = d1; s_bi[cbn * 256 + 128 + tid] = i0 + 1; cbn++; }
                        else { insert16(d1, i0 + 1, bdb, bib); tb = bdb[KNN - 1]; }
                    }
                }
            }
        }
        // flush buffers
        for (int u = 0; u < ca; ++u) {
            float d = s_bd[u * 256 + tid];
            if (d < ta) { insert16(d, s_bi[u * 256 + tid], bda, bia); ta = bda[KNN - 1]; }
        }
        ca = 0;
        for (int u = 0; u < cbn; ++u) {
            float d = s_bd[u * 256 + 128 + tid];
            if (d < tb) { insert16(d, s_bi[u * 256 + 128 + tid], bdb, bib); tb = bdb[KNN - 1]; }
        }
        cbn = 0;
    }

    {
        const int qg = b * NPTS + qa;
        float* pd = g_pd + ((size_t)chunk * NQ + qg) * KNN;
        int*   pi = g_pi + ((size_t)chunk * NQ + qg) * KNN;
#pragma unroll
        for (int j = 0; j < KNN; ++j) { pd[j] = bda[j]; pi[j] = bia[j]; }
    }
    {
        const int qg = b * NPTS + qb;
        float* pd = g_pd + ((size_t)chunk * NQ + qg) * KNN;
        int*   pi = g_pi + ((size_t)chunk * NQ + qg) * KNN;
#pragma unroll
        for (int j = 0; j < KNN; ++j) { pd[j] = bdb[j]; pi[j] = bib[j]; }
    }
}

// ---------------------------------------------------------------------------
// Kernel 1b: merge sorted partials -> final top-16
// ---------------------------------------------------------------------------
__global__ void __launch_bounds__(256) knn_merge() {
    const int qg = blockIdx.x * 256 + threadIdx.x;
    float bd[KNN]; int bi[KNN];

    const float4* p0d = (const float4*)(g_pd + (size_t)qg * KNN);
    const int4*   p0i = (const int4*)(g_pi + (size_t)qg * KNN);
#pragma unroll
    for (int v = 0; v < 4; ++v) {
        float4 d4 = p0d[v]; int4 i4 = p0i[v];
        bd[4*v] = d4.x; bd[4*v+1] = d4.y; bd[4*v+2] = d4.z; bd[4*v+3] = d4.w;
        bi[4*v] = i4.x; bi[4*v+1] = i4.y; bi[4*v+2] = i4.z; bi[4*v+3] = i4.w;
    }
    float bd15 = bd[KNN - 1];

    for (int c = 1; c < CHUNKS; ++c) {
        const float* pd = g_pd + ((size_t)c * NQ + qg) * KNN;
        const int*   pi = g_pi + ((size_t)c * NQ + qg) * KNN;
        for (int j = 0; j < KNN; ++j) {
            float d = pd[j];
            if (d >= bd15) break;
            insert16(d, pi[j], bd, bi);
            bd15 = bd[KNN - 1];
        }
    }
    int* op = g_idx + (size_t)qg * KNN;
#pragma unroll
    for (int j = 0; j < KNN; ++j) op[j] = bi[j];
}

// ---------------------------------------------------------------------------
// Kernel W: precombine weights (no ReLU between pairs -> linear fold)
// ---------------------------------------------------------------------------
__global__ void __launch_bounds__(256) wprep(const float* __restrict__ w_theta1,
                                             const float* __restrict__ w_theta2,
                                             const float* __restrict__ w_gamma1,
                                             const float* __restrict__ w_gamma2) {
    __shared__ float s1[4096], s2[4096];
    const int t = threadIdx.x;
    for (int i = t; i < 4096; i += 256) { s1[i] = w_gamma1[i]; s2[i] = w_gamma2[i]; }
    __syncthreads();
    for (int i = t; i < 4096; i += 256) {
        int c = i >> 6, o = i & 63;
        float a = 0.f;
#pragma unroll 16
        for (int m = 0; m < 64; ++m) a = fmaf(s2[o * 64 + m], s1[m * 64 + c], a);
        g_WgT[c * 64 + o] = a;
    }
    if (t < 192) {
        int c3 = t / 64, o = t % 64;
        float a = 0.f;
#pragma unroll 16
        for (int m = 0; m < 64; ++m) a = fmaf(w_theta2[o * 64 + m], w_theta1[m * 3 + c3], a);
        g_WtT[c3 * 64 + o] = a;
    }
}

// ---------------------------------------------------------------------------
// Kernel 2: feat3[b,n,o] = sum_c w_lin[o,c] * features[b,c,n]
// ---------------------------------------------------------------------------
__global__ void __launch_bounds__(128) feat3_kernel(const float* __restrict__ features,
                                                    const float* __restrict__ w_lin) {
    __shared__ float sw[F3 * CIN];
    for (int i = threadIdx.x; i < F3 * CIN; i += 128) sw[i] = w_lin[i];

    const int b = blockIdx.y;
    const int n = blockIdx.x * 128 + threadIdx.x;

    float f[CIN];
    const float* fb = features + (size_t)b * CIN * NPTS + n;
#pragma unroll
    for (int c = 0; c < CIN; ++c) f[c] = fb[(size_t)c * NPTS];
    __syncthreads();

    float* outp = g_feat3 + ((size_t)b * NPTS + n) * F3;
    const float4* sw4 = (const float4*)sw;
#pragma unroll 1
    for (int og = 0; og < F3 / 4; ++og) {
        float a0 = 0.f, a1 = 0.f, a2 = 0.f, a3 = 0.f;
#pragma unroll
        for (int c4 = 0; c4 < CIN / 4; ++c4) {
            float4 w0 = sw4[(og * 4 + 0) * 16 + c4];
            float4 w1 = sw4[(og * 4 + 1) * 16 + c4];
            float4 w2 = sw4[(og * 4 + 2) * 16 + c4];
            float4 w3 = sw4[(og * 4 + 3) * 16 + c4];
            int c = c4 * 4;
            a0 = fmaf(w0.x, f[c], fmaf(w0.y, f[c+1], fmaf(w0.z, f[c+2], fmaf(w0.w, f[c+3], a0))));
            a1 = fmaf(w1.x, f[c], fmaf(w1.y, f[c+1], fmaf(w1.z, f[c+2], fmaf(w1.w, f[c+3], a1))));
            a2 = fmaf(w2.x, f[c], fmaf(w2.y, f[c+1], fmaf(w2.z, f[c+2], fmaf(w2.w, f[c+3], a2))));
            a3 = fmaf(w3.x, f[c], fmaf(w3.y, f[c+1], fmaf(w3.z, f[c+2], fmaf(w3.w, f[c+3], a3))));
        }
        ((float4*)outp)[og] = make_float4(a0, a1, a2, a3);
    }
}

// ---------------------------------------------------------------------------
// Kernel 3: fused attention — one warp per point.
// lane = kh*16 + og; thread owns o in [4og,4og+4) x k in [8kh,8kh+8).
// ---------------------------------------------------------------------------
#define TEAMS 8
#define SM_STAGE 8384   // float offset of team staging (32KB wdup + 768B wt)
__global__ void __launch_bounds__(256) fused_kernel(const float* __restrict__ coords,
                                                    float* __restrict__ out) {
    extern __shared__ float sm[];
    ull*   sWgd = (ull*)sm;            // [c][o] duplicated pairs, 4096 ull = 32KB
    float* sWtT = sm + 8192;           // [c3][o] 192 floats

    const int tid = threadIdx.x;
    for (int i = tid; i < 4096; i += 256) sWgd[i] = pack2(g_WgT[i]);
    if (tid < 192) sWtT[tid] = g_WtT[tid];
    __syncthreads();

    const int team = tid >> 5;
    const int lane = tid & 31;
    const int og = lane & 15;
    const int kh = lane >> 4;
    const int k = lane & 15;        // gather role
    const int half = lane >> 4;     // gather role: c-range half

    const int P = blockIdx.x * TEAMS + team;
    const int b = P >> 13;
    const int n = P & (NPTS - 1);

    float* ig = sm + SM_STAGE + team * 2560;   // [64][CS]
    float* AG = ig + 1280;                     // [64][CS]

    // ---- gather + delta ----
    {
        int ik = g_idx[(size_t)P * KNN + k];
        const float* cbp = coords + (size_t)b * 3 * NPTS;
        float rx = cbp[n]            - cbp[ik];
        float ry = cbp[NPTS + n]     - cbp[NPTS + ik];
        float rz = cbp[2 * NPTS + n] - cbp[2 * NPTS + ik];

        const float* fb = g_feat3 + (size_t)(b * NPTS + ik) * F3;
        const float* fq = g_feat3 + (size_t)P * F3;
#pragma unroll
        for (int c4 = 0; c4 < 8; ++c4) {
            int c = half * 32 + c4 * 4;
            float4 ph = *(const float4*)(fq + c);
            float4 ps = *(const float4*)(fb + 64 + c);
            float4 al = *(const float4*)(fb + 128 + c);
            float4 w0 = *(const float4*)(sWtT + c);
            float4 w1 = *(const float4*)(sWtT + 64 + c);
            float4 w2 = *(const float4*)(sWtT + 128 + c);
            float d0 = fmaxf(fmaf(w2.x, rz, fmaf(w1.x, ry, w0.x * rx)), 0.f);
            float d1 = fmaxf(fmaf(w2.y, rz, fmaf(w1.y, ry, w0.y * rx)), 0.f);
            float d2 = fmaxf(fmaf(w2.z, rz, fmaf(w1.z, ry, w0.z * rx)), 0.f);
            float d3 = fmaxf(fmaf(w2.w, rz, fmaf(w1.w, ry, w0.w * rx)), 0.f);
            ig[(c + 0) * CS + k] = ph.x - ps.x + d0;
            ig[(c + 1) * CS + k] = ph.y - ps.y + d1;
            ig[(c + 2) * CS + k] = ph.z - ps.z + d2;
            ig[(c + 3) * CS + k] = ph.w - ps.w + d3;
            AG[(c + 0) * CS + k] = al.x + d0;
            AG[(c + 1) * CS + k] = al.y + d1;
            AG[(c + 2) * CS + k] = al.z + d2;
            AG[(c + 3) * CS + k] = al.w + d3;
        }
    }
    __syncwarp();

    // ---- g = relu(Wg @ ig), 4o x 8k per thread ----
    ull acc[16];
#pragma unroll
    for (int p = 0; p < 16; ++p) acc[p] = 0ull;
    {
        const ull* wbase = sWgd + 4 * og;
        const float* vbase = ig + kh * 8;
#pragma unroll 8
        for (int c = 0; c < 64; ++c) {
            ulonglong2 wa = *(const ulonglong2*)(wbase + c * 64);
            ulonglong2 wb = *(const ulonglong2*)(wbase + c * 64 + 2);
            ulonglong2 va = *(const ulonglong2*)(vbase + c * CS);
            ulonglong2 vb = *(const ulonglong2*)(vbase + c * CS + 4);
            fma2(acc[0],  wa.x, va.x); fma2(acc[1],  wa.x, va.y);
            fma2(acc[2],  wa.x, vb.x); fma2(acc[3],  wa.x, vb.y);
            fma2(acc[4],  wa.y, va.x); fma2(acc[5],  wa.y, va.y);
            fma2(acc[6],  wa.y, vb.x); fma2(acc[7],  wa.y, vb.y);
            fma2(acc[8],  wb.x, va.x); fma2(acc[9],  wb.x, va.y);
            fma2(acc[10], wb.x, vb.x); fma2(acc[11], wb.x, vb.y);
            fma2(acc[12], wb.y, va.x); fma2(acc[13], wb.y, va.y);
            fma2(acc[14], wb.y, vb.x); fma2(acc[15], wb.y, vb.y);
        }
    }

    // ---- softmax over k + weighted sum ----
#pragma unroll
    for (int i = 0; i < 4; ++i) {
        float g0 = fmaxf(f2lo(acc[i*4+0]), 0.f), g1 = fmaxf(f2hi(acc[i*4+0]), 0.f);
        float g2 = fmaxf(f2lo(acc[i*4+1]), 0.f), g3 = fmaxf(f2hi(acc[i*4+1]), 0.f);
        float g4 = fmaxf(f2lo(acc[i*4+2]), 0.f), g5 = fmaxf(f2hi(acc[i*4+2]), 0.f);
        float g6 = fmaxf(f2lo(acc[i*4+3]), 0.f), g7 = fmaxf(f2hi(acc[i*4+3]), 0.f);
        float m = fmaxf(fmaxf(fmaxf(g0, g1), fmaxf(g2, g3)),
                        fmaxf(fmaxf(g4, g5), fmaxf(g6, g7)));
        m = fmaxf(m, __shfl_xor_sync(0xffffffffu, m, 16));
        float e0 = __expf(g0 - m), e1 = __expf(g1 - m);
        float e2 = __expf(g2 - m), e3 = __expf(g3 - m);
        float e4 = __expf(g4 - m), e5 = __expf(g5 - m);
        float e6 = __expf(g6 - m), e7 = __expf(g7 - m);
        float s = ((e0 + e1) + (e2 + e3)) + ((e4 + e5) + (e6 + e7));
        const float* ap = AG + (4 * og + i) * CS + kh * 8;
        float4 a0 = *(const float4*)ap;
        float4 a1 = *(const float4*)(ap + 4);
        float num = fmaf(e0, a0.x, fmaf(e1, a0.y, fmaf(e2, a0.z, e3 * a0.w)));
        num = fmaf(e4, a1.x, fmaf(e5, a1.y, fmaf(e6, a1.z, fmaf(e7, a1.w, num))));
        s   += __shfl_xor_sync(0xffffffffu, s, 16);
        num += __shfl_xor_sync(0xffffffffu, num, 16);
        if (kh == 0)
            out[((size_t)b * CO + 4 * og + i) * NPTS + n] = num / s;
    }
}

// ---------------------------------------------------------------------------
#define FUSED_SMEM ((SM_STAGE + TEAMS * 2560) * sizeof(float))
extern "C" void kernel_launch(void* const* d_in, const int* in_sizes, int n_in,
                              void* d_out, int out_size) {
    const float* features = (const float*)d_in[0];
    const float* coords   = (const float*)d_in[1];
    const float* w_lin    = (const float*)d_in[2];
    const float* w_theta1 = (const float*)d_in[3];
    const float* w_theta2 = (const float*)d_in[4];
    const float* w_gamma1 = (const float*)d_in[5];
    const float* w_gamma2 = (const float*)d_in[6];
    float* out = (float*)d_out;

    static bool attr_set = false;
    if (!attr_set) {
        cudaFuncSetAttribute(fused_kernel, cudaFuncAttributeMaxDynamicSharedMemorySize,
                             FUSED_SMEM);
        attr_set = true;
    }

    knn_part<<<dim3(NPTS / QPB, BATCH, CHUNKS), 128>>>(coords);
    wprep<<<1, 256>>>(w_theta1, w_theta2, w_gamma1, w_gamma2);
    feat3_kernel<<<dim3(NPTS / 128, BATCH), 128>>>(features, w_lin);
    knn_merge<<<NQ / 256, 256>>>();
    fused_kernel<<<NQ / TEAMS, 256, FUSED_SMEM>>>(coords, out);
}

// round 6
// speedup vs baseline: 1.5129x; 1.5129x over previous
#include <cuda_runtime.h>
#include <cstdint>

#define BATCH 4
#define NPTS  8192
#define KNN   16
#define CIN   64
#define CO    64
#define F3    192
#define CS    20
#define PPT   4
#define NQ    (BATCH * NPTS)
#define CHUNKS 4
#define CPC   (NPTS / CHUNKS)     // 2048 candidates per chunk
#define CPAIRS (CPC / 2)          // 1024 pairs

typedef unsigned long long ull;
typedef unsigned int uint;

__device__ int   g_idx[NQ * KNN];
__device__ float g_feat3[(size_t)NQ * F3];
__device__ float g_pd[CHUNKS * NQ * KNN];
__device__ int   g_pi[CHUNKS * NQ * KNN];
__device__ float g_WgT[CO * CO];   // [c][o] = (w_gamma2 @ w_gamma1)^T
__device__ float g_WtT[3 * CO];    // [c3][o] = (w_theta2 @ w_theta1)^T

// ---------------------------------------------------------------------------
// packed f32x2 helpers
// ---------------------------------------------------------------------------
__device__ __forceinline__ ull pack2(float f) {
    ull r; uint u = __float_as_uint(f);
    asm("mov.b64 %0, {%1, %1};" : "=l"(r) : "r"(u));
    return r;
}
__device__ __forceinline__ ull packpair(float lo, float hi) {
    ull r;
    asm("mov.b64 %0, {%1, %2};" : "=l"(r) : "r"(__float_as_uint(lo)), "r"(__float_as_uint(hi)));
    return r;
}
__device__ __forceinline__ void fma2(ull& acc, ull a, ull b) {
    asm("fma.rn.f32x2 %0, %1, %2, %0;" : "+l"(acc) : "l"(a), "l"(b));
}
__device__ __forceinline__ float f2lo(ull v) { return __uint_as_float((uint)v); }
__device__ __forceinline__ float f2hi(ull v) { return __uint_as_float((uint)(v >> 32)); }

// ---------------------------------------------------------------------------
__device__ __forceinline__ void insert16(float d, int id, float bd[KNN], int bi[KNN]) {
#pragma unroll
    for (int t = 0; t < KNN; ++t) {
        bool p = d < bd[t];
        float td = bd[t]; int ti = bi[t];
        bd[t] = p ? d : bd[t];
        bi[t] = p ? id : bi[t];
        d  = p ? td : d;
        id = p ? ti : id;
    }
}

// ---------------------------------------------------------------------------
// Kernel 1: partial KNN. ONE query/thread, f32x2 pair-packed candidates,
// geometric-window deferred insertion. key = |m|^2 - 2 q.m
// ---------------------------------------------------------------------------
__global__ void __launch_bounds__(256) knn_part(const float* __restrict__ coords) {
    extern __shared__ ull s_dyn[];
    ull*   s_pt = s_dyn;                        // [CPAIRS][4]  32KB
    float* s_bd = (float*)(s_dyn + CPAIRS * 4); // [KNN][256]   16KB
    int*   s_bi = (int*)(s_bd + KNN * 256);     // [KNN][256]   16KB

    const int tid = threadIdx.x;
    const int b = blockIdx.y;
    const int chunk = blockIdx.z;
    const int q = blockIdx.x * 256 + tid;
    const float* cb = coords + (size_t)b * 3 * NPTS;
    const int cbase = chunk * CPC;

    // pack candidate tile: {x2, y2, z2, |p|^2 x2}
    for (int jp = tid; jp < CPAIRS; jp += 256) {
        float2 x = *(const float2*)(cb + cbase + 2 * jp);
        float2 y = *(const float2*)(cb + NPTS + cbase + 2 * jp);
        float2 z = *(const float2*)(cb + 2 * NPTS + cbase + 2 * jp);
        float w0 = fmaf(z.x, z.x, fmaf(y.x, y.x, x.x * x.x));
        float w1 = fmaf(z.y, z.y, fmaf(y.y, y.y, x.y * x.y));
        ull* p = s_pt + (size_t)jp * 4;
        p[0] = packpair(x.x, x.y);
        p[1] = packpair(y.x, y.y);
        p[2] = packpair(z.x, z.y);
        p[3] = packpair(w0, w1);
    }

    const ull nx = pack2(-2.f * cb[q]);
    const ull ny = pack2(-2.f * cb[NPTS + q]);
    const ull nz = pack2(-2.f * cb[2 * NPTS + q]);

    float bd[KNN]; int bi[KNN];
#pragma unroll
    for (int j = 0; j < KNN; ++j) { bd[j] = 3.4e38f; bi[j] = 0; }
    float thr = 3.4e38f;
    int cnt = 0;
    __syncthreads();

    // geometric windows over pair index: (0,8),(8,16),(16,32),...,(512,1024)
    for (int w = 0; w < 8; ++w) {
        const int j0 = (w == 0) ? 0 : (4 << w);
        const int j1 = 8 << w;
#pragma unroll 4
        for (int jp = j0; jp < j1; ++jp) {
            ulonglong2 p01 = *(const ulonglong2*)(s_pt + (size_t)jp * 4);
            ulonglong2 p23 = *(const ulonglong2*)(s_pt + (size_t)jp * 4 + 2);
            ull d2 = p23.y;
            fma2(d2, nz, p23.x);
            fma2(d2, ny, p01.y);
            fma2(d2, nx, p01.x);
            float d0 = f2lo(d2), d1 = f2hi(d2);
            if (fminf(d0, d1) < thr) {
                const int i0 = cbase + 2 * jp;
                if (d0 < thr) {
                    if (cnt < KNN) { s_bd[cnt * 256 + tid] = d0; s_bi[cnt * 256 + tid] = i0; cnt++; }
                    else { insert16(d0, i0, bd, bi); thr = bd[KNN - 1]; }
                }
                if (d1 < thr) {
                    if (cnt < KNN) { s_bd[cnt * 256 + tid] = d1; s_bi[cnt * 256 + tid] = i0 + 1; cnt++; }
                    else { insert16(d1, i0 + 1, bd, bi); thr = bd[KNN - 1]; }
                }
            }
        }
        // flush deferred hits
        for (int u = 0; u < cnt; ++u) {
            float d = s_bd[u * 256 + tid];
            if (d < thr) {
                insert16(d, s_bi[u * 256 + tid], bd, bi);
                thr = bd[KNN - 1];
            }
        }
        cnt = 0;
    }

    const int qg = b * NPTS + q;
    float* pd = g_pd + ((size_t)chunk * NQ + qg) * KNN;
    int*   pi = g_pi + ((size_t)chunk * NQ + qg) * KNN;
#pragma unroll
    for (int j = 0; j < KNN; ++j) { pd[j] = bd[j]; pi[j] = bi[j]; }
}
#define KNN_SMEM (CPAIRS * 4 * sizeof(ull) + KNN * 256 * (sizeof(float) + sizeof(int)))

// ---------------------------------------------------------------------------
// Kernel 1b: merge sorted partials -> final top-16
// ---------------------------------------------------------------------------
__global__ void __launch_bounds__(256) knn_merge() {
    const int qg = blockIdx.x * 256 + threadIdx.x;
    float bd[KNN]; int bi[KNN];

    const float4* p0d = (const float4*)(g_pd + (size_t)qg * KNN);
    const int4*   p0i = (const int4*)(g_pi + (size_t)qg * KNN);
#pragma unroll
    for (int v = 0; v < 4; ++v) {
        float4 d4 = p0d[v]; int4 i4 = p0i[v];
        bd[4*v] = d4.x; bd[4*v+1] = d4.y; bd[4*v+2] = d4.z; bd[4*v+3] = d4.w;
        bi[4*v] = i4.x; bi[4*v+1] = i4.y; bi[4*v+2] = i4.z; bi[4*v+3] = i4.w;
    }
    float bd15 = bd[KNN - 1];

    for (int c = 1; c < CHUNKS; ++c) {
        const float* pd = g_pd + ((size_t)c * NQ + qg) * KNN;
        const int*   pi = g_pi + ((size_t)c * NQ + qg) * KNN;
        for (int j = 0; j < KNN; ++j) {
            float d = pd[j];
            if (d >= bd15) break;
            insert16(d, pi[j], bd, bi);
            bd15 = bd[KNN - 1];
        }
    }
    int* op = g_idx + (size_t)qg * KNN;
#pragma unroll
    for (int j = 0; j < KNN; ++j) op[j] = bi[j];
}

// ---------------------------------------------------------------------------
// Kernel W: precombine weights (no ReLU between pairs -> linear fold)
// ---------------------------------------------------------------------------
__global__ void __launch_bounds__(256) wprep(const float* __restrict__ w_theta1,
                                             const float* __restrict__ w_theta2,
                                             const float* __restrict__ w_gamma1,
                                             const float* __restrict__ w_gamma2) {
    __shared__ float s1[4096], s2[4096];
    const int t = threadIdx.x;
    for (int i = t; i < 4096; i += 256) { s1[i] = w_gamma1[i]; s2[i] = w_gamma2[i]; }
    __syncthreads();
    for (int i = t; i < 4096; i += 256) {
        int c = i >> 6, o = i & 63;
        float a = 0.f;
#pragma unroll 16
        for (int m = 0; m < 64; ++m) a = fmaf(s2[o * 64 + m], s1[m * 64 + c], a);
        g_WgT[c * 64 + o] = a;
    }
    if (t < 192) {
        int c3 = t / 64, o = t % 64;
        float a = 0.f;
#pragma unroll 16
        for (int m = 0; m < 64; ++m) a = fmaf(w_theta2[o * 64 + m], w_theta1[m * 3 + c3], a);
        g_WtT[c3 * 64 + o] = a;
    }
}

// ---------------------------------------------------------------------------
// Kernel 2: feat3[b,n,o] = sum_c w_lin[o,c] * features[b,c,n]
// ---------------------------------------------------------------------------
__global__ void __launch_bounds__(128) feat3_kernel(const float* __restrict__ features,
                                                    const float* __restrict__ w_lin) {
    __shared__ float sw[F3 * CIN];
    for (int i = threadIdx.x; i < F3 * CIN; i += 128) sw[i] = w_lin[i];

    const int b = blockIdx.y;
    const int n = blockIdx.x * 128 + threadIdx.x;

    float f[CIN];
    const float* fb = features + (size_t)b * CIN * NPTS + n;
#pragma unroll
    for (int c = 0; c < CIN; ++c) f[c] = fb[(size_t)c * NPTS];
    __syncthreads();

    float* outp = g_feat3 + ((size_t)b * NPTS + n) * F3;
    const float4* sw4 = (const float4*)sw;
#pragma unroll 1
    for (int og = 0; og < F3 / 4; ++og) {
        float a0 = 0.f, a1 = 0.f, a2 = 0.f, a3 = 0.f;
#pragma unroll
        for (int c4 = 0; c4 < CIN / 4; ++c4) {
            float4 w0 = sw4[(og * 4 + 0) * 16 + c4];
            float4 w1 = sw4[(og * 4 + 1) * 16 + c4];
            float4 w2 = sw4[(og * 4 + 2) * 16 + c4];
            float4 w3 = sw4[(og * 4 + 3) * 16 + c4];
            int c = c4 * 4;
            a0 = fmaf(w0.x, f[c], fmaf(w0.y, f[c+1], fmaf(w0.z, f[c+2], fmaf(w0.w, f[c+3], a0))));
            a1 = fmaf(w1.x, f[c], fmaf(w1.y, f[c+1], fmaf(w1.z, f[c+2], fmaf(w1.w, f[c+3], a1))));
            a2 = fmaf(w2.x, f[c], fmaf(w2.y, f[c+1], fmaf(w2.z, f[c+2], fmaf(w2.w, f[c+3], a2))));
            a3 = fmaf(w3.x, f[c], fmaf(w3.y, f[c+1], fmaf(w3.z, f[c+2], fmaf(w3.w, f[c+3], a3))));
        }
        ((float4*)outp)[og] = make_float4(a0, a1, a2, a3);
    }
}

// ---------------------------------------------------------------------------
__device__ __forceinline__ void gemm64(ull acc[8], const float* __restrict__ wcolT,
                                       const float* __restrict__ vrow) {
#pragma unroll
    for (int p = 0; p < 8; ++p) acc[p] = 0ull;
#pragma unroll 16
    for (int c = 0; c < 64; ++c) {
        float4 w = *(const float4*)(wcolT + c * 64);
        double2 vv = *(const double2*)(vrow + c * CS);
        ull v0 = __double_as_longlong(vv.x);
        ull v1 = __double_as_longlong(vv.y);
        ull w0 = pack2(w.x), w1 = pack2(w.y), w2 = pack2(w.z), w3 = pack2(w.w);
        fma2(acc[0], w0, v0); fma2(acc[1], w0, v1);
        fma2(acc[2], w1, v0); fma2(acc[3], w1, v1);
        fma2(acc[4], w2, v0); fma2(acc[5], w2, v1);
        fma2(acc[6], w3, v0); fma2(acc[7], w3, v1);
    }
}

#define TEAM_BAR() asm volatile("bar.sync %0, 64;" :: "r"(barid) : "memory")

// ---------------------------------------------------------------------------
// Kernel 3: fused attention, single folded gamma GEMM per (n,k).
// 256 threads = 4 teams of 64; team = one point. (round-4 proven version)
// ---------------------------------------------------------------------------
#define TA 2560
__global__ void __launch_bounds__(256) fused_kernel(const float* __restrict__ coords,
                                                    float* __restrict__ out) {
    extern __shared__ float sm[];
    float* sWgT = sm;            // 4096  [c][o]
    float* sWtT = sm + 4096;     // 192   [c3][o]

    const int tid = threadIdx.x;
    for (int i = tid; i < 4096; i += 256) sWgT[i] = g_WgT[i];
    if (tid < 192) sWtT[tid] = g_WtT[tid];
    __syncthreads();

    const int gq  = tid >> 6;
    const int t64 = tid & 63;
    const int og  = t64 >> 2;
    const int kg  = t64 & 3;
    const int k    = t64 & 15;
    const int half = t64 >> 4;
    const int barid = gq + 1;

    float* ig = sm + 4288 + gq * TA;   // [64][CS]
    float* AG = ig + 1280;             // [64][CS]

    for (int P = blockIdx.x * PPT + gq; P < NQ; P += gridDim.x * PPT) {
        const int b = P >> 13;
        const int n = P & (NPTS - 1);

        // ---- gather + delta + staging ----
        {
            int ik = g_idx[(size_t)P * KNN + k];
            const float* cb = coords + (size_t)b * 3 * NPTS;
            float rx = cb[n]            - cb[ik];
            float ry = cb[NPTS + n]     - cb[NPTS + ik];
            float rz = cb[2 * NPTS + n] - cb[2 * NPTS + ik];

            const float* fb = g_feat3 + (size_t)(b * NPTS + ik) * F3;
            const float* fq = g_feat3 + (size_t)P * F3;
#pragma unroll
            for (int c4 = 0; c4 < 4; ++c4) {
                int c = half * 16 + c4 * 4;
                float4 ph = *(const float4*)(fq + c);
                float4 ps = *(const float4*)(fb + 64 + c);
                float4 al = *(const float4*)(fb + 128 + c);
                float4 w0 = *(const float4*)(sWtT + c);
                float4 w1 = *(const float4*)(sWtT + 64 + c);
                float4 w2 = *(const float4*)(sWtT + 128 + c);
                float d0 = fmaxf(fmaf(w2.x, rz, fmaf(w1.x, ry, w0.x * rx)), 0.f);
                float d1 = fmaxf(fmaf(w2.y, rz, fmaf(w1.y, ry, w0.y * rx)), 0.f);
                float d2 = fmaxf(fmaf(w2.z, rz, fmaf(w1.z, ry, w0.z * rx)), 0.f);
                float d3 = fmaxf(fmaf(w2.w, rz, fmaf(w1.w, ry, w0.w * rx)), 0.f);
                ig[(c + 0) * CS + k] = ph.x - ps.x + d0;
                ig[(c + 1) * CS + k] = ph.y - ps.y + d1;
                ig[(c + 2) * CS + k] = ph.z - ps.z + d2;
                ig[(c + 3) * CS + k] = ph.w - ps.w + d3;
                AG[(c + 0) * CS + k] = al.x + d0;
                AG[(c + 1) * CS + k] = al.y + d1;
                AG[(c + 2) * CS + k] = al.z + d2;
                AG[(c + 3) * CS + k] = al.w + d3;
            }
        }
        TEAM_BAR();

        // ---- g = relu(Wg @ ig); softmax over k; weighted sum ----
        ull acc[8];
        gemm64(acc, sWgT + 4 * og, ig + 4 * kg);
#pragma unroll
        for (int i = 0; i < 4; ++i) {
            float g0 = fmaxf(f2lo(acc[2*i]),   0.f);
            float g1 = fmaxf(f2hi(acc[2*i]),   0.f);
            float g2 = fmaxf(f2lo(acc[2*i+1]), 0.f);
            float g3 = fmaxf(f2hi(acc[2*i+1]), 0.f);
            float m = fmaxf(fmaxf(g0, g1), fmaxf(g2, g3));
            m = fmaxf(m, __shfl_xor_sync(0xffffffffu, m, 1));
            m = fmaxf(m, __shfl_xor_sync(0xffffffffu, m, 2));
            float e0 = __expf(g0 - m), e1 = __expf(g1 - m);
            float e2 = __expf(g2 - m), e3 = __expf(g3 - m);
            float s = (e0 + e1) + (e2 + e3);
            float4 a = *(const float4*)&AG[(4 * og + i) * CS + 4 * kg];
            float num = fmaf(e0, a.x, fmaf(e1, a.y, fmaf(e2, a.z, e3 * a.w)));
            s   += __shfl_xor_sync(0xffffffffu, s, 1);
            num += __shfl_xor_sync(0xffffffffu, num, 1);
            s   += __shfl_xor_sync(0xffffffffu, s, 2);
            num += __shfl_xor_sync(0xffffffffu, num, 2);
            if (kg == 0)
                out[((size_t)b * CO + 4 * og + i) * NPTS + n] = num / s;
        }
        TEAM_BAR();
    }
}

// ---------------------------------------------------------------------------
#define FUSED_SMEM ((4288 + PPT * TA) * sizeof(float))
extern "C" void kernel_launch(void* const* d_in, const int* in_sizes, int n_in,
                              void* d_out, int out_size) {
    const float* features = (const float*)d_in[0];
    const float* coords   = (const float*)d_in[1];
    const float* w_lin    = (const float*)d_in[2];
    const float* w_theta1 = (const float*)d_in[3];
    const float* w_theta2 = (const float*)d_in[4];
    const float* w_gamma1 = (const float*)d_in[5];
    const float* w_gamma2 = (const float*)d_in[6];
    float* out = (float*)d_out;

    static bool attr_set = false;
    if (!attr_set) {
        cudaFuncSetAttribute(fused_kernel, cudaFuncAttributeMaxDynamicSharedMemorySize,
                             FUSED_SMEM);
        cudaFuncSetAttribute(knn_part, cudaFuncAttributeMaxDynamicSharedMemorySize,
                             KNN_SMEM);
        attr_set = true;
    }

    knn_part<<<dim3(NPTS / 256, BATCH, CHUNKS), 256, KNN_SMEM>>>(coords);
    wprep<<<1, 256>>>(w_theta1, w_theta2, w_gamma1, w_gamma2);
    feat3_kernel<<<dim3(NPTS / 128, BATCH), 128>>>(features, w_lin);
    knn_merge<<<NQ / 256, 256>>>();
    fused_kernel<<<2048, 256, FUSED_SMEM>>>(coords, out);
}

// round 7
// speedup vs baseline: 1.6140x; 1.0669x over previous
#include <cuda_runtime.h>
#include <cstdint>

#define BATCH 4
#define NPTS  8192
#define KNN   16
#define CIN   64
#define CO    64
#define F3    192
#define CS    20
#define PPT   4
#define NQ    (BATCH * NPTS)
#define QB    64                  // queries per knn block
#define TPAIRS 1024               // candidate pairs per smem tile (2048 cands)
#define NTILES (NPTS / (2 * TPAIRS))   // 4

typedef unsigned long long ull;
typedef unsigned int uint;

__device__ int   g_idx[NQ * KNN];
__device__ float g_feat3[(size_t)NQ * F3];
__device__ float g_WgT[CO * CO];   // [c][o] = (w_gamma2 @ w_gamma1)^T
__device__ float g_WtT[3 * CO];    // [c3][o] = (w_theta2 @ w_theta1)^T

// ---------------------------------------------------------------------------
// packed f32x2 helpers
// ---------------------------------------------------------------------------
__device__ __forceinline__ ull pack2(float f) {
    ull r; uint u = __float_as_uint(f);
    asm("mov.b64 %0, {%1, %1};" : "=l"(r) : "r"(u));
    return r;
}
__device__ __forceinline__ ull packpair(float lo, float hi) {
    ull r;
    asm("mov.b64 %0, {%1, %2};" : "=l"(r) : "r"(__float_as_uint(lo)), "r"(__float_as_uint(hi)));
    return r;
}
__device__ __forceinline__ void fma2(ull& acc, ull a, ull b) {
    asm("fma.rn.f32x2 %0, %1, %2, %0;" : "+l"(acc) : "l"(a), "l"(b));
}
__device__ __forceinline__ float f2lo(ull v) { return __uint_as_float((uint)v); }
__device__ __forceinline__ float f2hi(ull v) { return __uint_as_float((uint)(v >> 32)); }

// ---------------------------------------------------------------------------
__device__ __forceinline__ void insert16(float d, int id, float bd[KNN], int bi[KNN]) {
#pragma unroll
    for (int t = 0; t < KNN; ++t) {
        bool p = d < bd[t];
        float td = bd[t]; int ti = bi[t];
        bd[t] = p ? d : bd[t];
        bi[t] = p ? id : bi[t];
        d  = p ? td : d;
        id = p ? ti : id;
    }
}

// ---------------------------------------------------------------------------
// KNN state + windowed scan helper
// ---------------------------------------------------------------------------
struct KS {
    float bd[KNN]; int bi[KNN];
    float thr; int cnt;
};

__device__ __forceinline__ void scan_window(const ull* __restrict__ s_pt,
                                            int j0, int j1, int ibase,
                                            ull nx, ull ny, ull nz,
                                            KS& st, float* s_bd, int* s_bi, int tid) {
#pragma unroll 4
    for (int jp = j0; jp < j1; ++jp) {
        ulonglong2 p01 = *(const ulonglong2*)(s_pt + (size_t)jp * 4);
        ulonglong2 p23 = *(const ulonglong2*)(s_pt + (size_t)jp * 4 + 2);
        ull d2 = p23.y;
        fma2(d2, nz, p23.x);
        fma2(d2, ny, p01.y);
        fma2(d2, nx, p01.x);
        float d0 = f2lo(d2), d1 = f2hi(d2);
        if (fminf(d0, d1) < st.thr) {
            const int i0 = ibase + 2 * jp;
            if (d0 < st.thr) {
                if (st.cnt < KNN) { s_bd[st.cnt * QB + tid] = d0; s_bi[st.cnt * QB + tid] = i0; st.cnt++; }
                else { insert16(d0, i0, st.bd, st.bi); st.thr = st.bd[KNN - 1]; }
            }
            if (d1 < st.thr) {
                if (st.cnt < KNN) { s_bd[st.cnt * QB + tid] = d1; s_bi[st.cnt * QB + tid] = i0 + 1; st.cnt++; }
                else { insert16(d1, i0 + 1, st.bd, st.bi); st.thr = st.bd[KNN - 1]; }
            }
        }
    }
    for (int u = 0; u < st.cnt; ++u) {
        float d = s_bd[u * QB + tid];
        if (d < st.thr) {
            insert16(d, s_bi[u * QB + tid], st.bd, st.bi);
            st.thr = st.bd[KNN - 1];
        }
    }
    st.cnt = 0;
}

// ---------------------------------------------------------------------------
// Kernel 1: full KNN, sequential tiles, top-16 carried across tiles.
// key = |m|^2 - 2 q.m  (query norm dropped; order-preserving)
// ---------------------------------------------------------------------------
__global__ void __launch_bounds__(QB) knn_kernel(const float* __restrict__ coords) {
    extern __shared__ ull s_dyn[];
    ull*   s_pt = s_dyn;                          // [TPAIRS][4]  32KB
    float* s_bd = (float*)(s_dyn + TPAIRS * 4);   // [KNN][QB]    4KB
    int*   s_bi = (int*)(s_bd + KNN * QB);        // [KNN][QB]    4KB

    const int tid = threadIdx.x;
    const int b = blockIdx.y;
    const int q = blockIdx.x * QB + tid;
    const float* cb = coords + (size_t)b * 3 * NPTS;

    const ull nx = pack2(-2.f * cb[q]);
    const ull ny = pack2(-2.f * cb[NPTS + q]);
    const ull nz = pack2(-2.f * cb[2 * NPTS + q]);

    KS st;
#pragma unroll
    for (int j = 0; j < KNN; ++j) { st.bd[j] = 3.4e38f; st.bi[j] = 0; }
    st.thr = 3.4e38f; st.cnt = 0;

    for (int tile = 0; tile < NTILES; ++tile) {
        const int cbase = tile * 2 * TPAIRS;
        __syncthreads();
        for (int jp = tid; jp < TPAIRS; jp += QB) {
            float2 x = *(const float2*)(cb + cbase + 2 * jp);
            float2 y = *(const float2*)(cb + NPTS + cbase + 2 * jp);
            float2 z = *(const float2*)(cb + 2 * NPTS + cbase + 2 * jp);
            float w0 = fmaf(z.x, z.x, fmaf(y.x, y.x, x.x * x.x));
            float w1 = fmaf(z.y, z.y, fmaf(y.y, y.y, x.y * x.y));
            ull* p = s_pt + (size_t)jp * 4;
            p[0] = packpair(x.x, x.y);
            p[1] = packpair(y.x, y.y);
            p[2] = packpair(z.x, z.y);
            p[3] = packpair(w0, w1);
        }
        __syncthreads();

        if (tile == 0) {
            // geometric windows: (0,8),(8,16),(16,32),...,(512,1024) pairs
            for (int w = 0; w < 8; ++w) {
                const int j0 = (w == 0) ? 0 : (4 << w);
                const int j1 = 8 << w;
                scan_window(s_pt, j0, j1, cbase, nx, ny, nz, st, s_bd, s_bi, tid);
            }
        } else {
            // whole tile as one window (expected hits ~16*ln((t+1)/t) <= 11)
            scan_window(s_pt, 0, TPAIRS, cbase, nx, ny, nz, st, s_bd, s_bi, tid);
        }
    }

    int* op = g_idx + ((size_t)b * NPTS + q) * KNN;
#pragma unroll
    for (int j = 0; j < KNN; ++j) op[j] = st.bi[j];
}
#define KNN_SMEM (TPAIRS * 4 * sizeof(ull) + KNN * QB * (sizeof(float) + sizeof(int)))

// ---------------------------------------------------------------------------
// Kernel W: precombine weights (no ReLU between pairs -> linear fold)
// ---------------------------------------------------------------------------
__global__ void __launch_bounds__(256) wprep(const float* __restrict__ w_theta1,
                                             const float* __restrict__ w_theta2,
                                             const float* __restrict__ w_gamma1,
                                             const float* __restrict__ w_gamma2) {
    __shared__ float s1[4096], s2[4096];
    const int t = threadIdx.x;
    for (int i = t; i < 4096; i += 256) { s1[i] = w_gamma1[i]; s2[i] = w_gamma2[i]; }
    __syncthreads();
    {
        int i = blockIdx.x * 256 + t;       // 16 blocks x 256 = 4096
        int c = i >> 6, o = i & 63;
        float a = 0.f;
#pragma unroll 16
        for (int m = 0; m < 64; ++m) a = fmaf(s2[o * 64 + m], s1[m * 64 + c], a);
        g_WgT[c * 64 + o] = a;
    }
    if (blockIdx.x == 0 && t < 192) {
        int c3 = t / 64, o = t % 64;
        float a = 0.f;
#pragma unroll 16
        for (int m = 0; m < 64; ++m) a = fmaf(w_theta2[o * 64 + m], w_theta1[m * 3 + c3], a);
        g_WtT[c3 * 64 + o] = a;
    }
}

// ---------------------------------------------------------------------------
// Kernel 2: feat3[b,n,o] = sum_c w_lin[o,c] * features[b,c,n]
// ---------------------------------------------------------------------------
__global__ void __launch_bounds__(128) feat3_kernel(const float* __restrict__ features,
                                                    const float* __restrict__ w_lin) {
    __shared__ float sw[F3 * CIN];
    for (int i = threadIdx.x; i < F3 * CIN; i += 128) sw[i] = w_lin[i];

    const int b = blockIdx.y;
    const int n = blockIdx.x * 128 + threadIdx.x;

    float f[CIN];
    const float* fb = features + (size_t)b * CIN * NPTS + n;
#pragma unroll
    for (int c = 0; c < CIN; ++c) f[c] = fb[(size_t)c * NPTS];
    __syncthreads();

    float* outp = g_feat3 + ((size_t)b * NPTS + n) * F3;
    const float4* sw4 = (const float4*)sw;
#pragma unroll 1
    for (int og = 0; og < F3 / 4; ++og) {
        float a0 = 0.f, a1 = 0.f, a2 = 0.f, a3 = 0.f;
#pragma unroll
        for (int c4 = 0; c4 < CIN / 4; ++c4) {
            float4 w0 = sw4[(og * 4 + 0) * 16 + c4];
            float4 w1 = sw4[(og * 4 + 1) * 16 + c4];
            float4 w2 = sw4[(og * 4 + 2) * 16 + c4];
            float4 w3 = sw4[(og * 4 + 3) * 16 + c4];
            int c = c4 * 4;
            a0 = fmaf(w0.x, f[c], fmaf(w0.y, f[c+1], fmaf(w0.z, f[c+2], fmaf(w0.w, f[c+3], a0))));
            a1 = fmaf(w1.x, f[c], fmaf(w1.y, f[c+1], fmaf(w1.z, f[c+2], fmaf(w1.w, f[c+3], a1))));
            a2 = fmaf(w2.x, f[c], fmaf(w2.y, f[c+1], fmaf(w2.z, f[c+2], fmaf(w2.w, f[c+3], a2))));
            a3 = fmaf(w3.x, f[c], fmaf(w3.y, f[c+1], fmaf(w3.z, f[c+2], fmaf(w3.w, f[c+3], a3))));
        }
        ((float4*)outp)[og] = make_float4(a0, a1, a2, a3);
    }
}

// ---------------------------------------------------------------------------
__device__ __forceinline__ void gemm64(ull acc[8], const float* __restrict__ wcolT,
                                       const float* __restrict__ vrow) {
#pragma unroll
    for (int p = 0; p < 8; ++p) acc[p] = 0ull;
#pragma unroll 16
    for (int c = 0; c < 64; ++c) {
        float4 w = *(const float4*)(wcolT + c * 64);
        double2 vv = *(const double2*)(vrow + c * CS);
        ull v0 = __double_as_longlong(vv.x);
        ull v1 = __double_as_longlong(vv.y);
        ull w0 = pack2(w.x), w1 = pack2(w.y), w2 = pack2(w.z), w3 = pack2(w.w);
        fma2(acc[0], w0, v0); fma2(acc[1], w0, v1);
        fma2(acc[2], w1, v0); fma2(acc[3], w1, v1);
        fma2(acc[4], w2, v0); fma2(acc[5], w2, v1);
        fma2(acc[6], w3, v0); fma2(acc[7], w3, v1);
    }
}

#define TEAM_BAR() asm volatile("bar.sync %0, 64;" :: "r"(barid) : "memory")

// ---------------------------------------------------------------------------
// Kernel 3: fused attention, single folded gamma GEMM per (n,k).
// 256 threads = 4 teams of 64; team = one point. (round-4 proven version)
// ---------------------------------------------------------------------------
#define TA 2560
__global__ void __launch_bounds__(256) fused_kernel(const float* __restrict__ coords,
                                                    float* __restrict__ out) {
    extern __shared__ float sm[];
    float* sWgT = sm;            // 4096  [c][o]
    float* sWtT = sm + 4096;     // 192   [c3][o]

    const int tid = threadIdx.x;
    for (int i = tid; i < 4096; i += 256) sWgT[i] = g_WgT[i];
    if (tid < 192) sWtT[tid] = g_WtT[tid];
    __syncthreads();

    const int gq  = tid >> 6;
    const int t64 = tid & 63;
    const int og  = t64 >> 2;
    const int kg  = t64 & 3;
    const int k    = t64 & 15;
    const int half = t64 >> 4;
    const int barid = gq + 1;

    float* ig = sm + 4288 + gq * TA;   // [64][CS]
    float* AG = ig + 1280;             // [64][CS]

    for (int P = blockIdx.x * PPT + gq; P < NQ; P += gridDim.x * PPT) {
        const int b = P >> 13;
        const int n = P & (NPTS - 1);

        // ---- gather + delta + staging ----
        {
            int ik = g_idx[(size_t)P * KNN + k];
            const float* cb = coords + (size_t)b * 3 * NPTS;
            float rx = cb[n]            - cb[ik];
            float ry = cb[NPTS + n]     - cb[NPTS + ik];
            float rz = cb[2 * NPTS + n] - cb[2 * NPTS + ik];

            const float* fb = g_feat3 + (size_t)(b * NPTS + ik) * F3;
            const float* fq = g_feat3 + (size_t)P * F3;
#pragma unroll
            for (int c4 = 0; c4 < 4; ++c4) {
                int c = half * 16 + c4 * 4;
                float4 ph = *(const float4*)(fq + c);
                float4 ps = *(const float4*)(fb + 64 + c);
                float4 al = *(const float4*)(fb + 128 + c);
                float4 w0 = *(const float4*)(sWtT + c);
                float4 w1 = *(const float4*)(sWtT + 64 + c);
                float4 w2 = *(const float4*)(sWtT + 128 + c);
                float d0 = fmaxf(fmaf(w2.x, rz, fmaf(w1.x, ry, w0.x * rx)), 0.f);
                float d1 = fmaxf(fmaf(w2.y, rz, fmaf(w1.y, ry, w0.y * rx)), 0.f);
                float d2 = fmaxf(fmaf(w2.z, rz, fmaf(w1.z, ry, w0.z * rx)), 0.f);
                float d3 = fmaxf(fmaf(w2.w, rz, fmaf(w1.w, ry, w0.w * rx)), 0.f);
                ig[(c + 0) * CS + k] = ph.x - ps.x + d0;
                ig[(c + 1) * CS + k] = ph.y - ps.y + d1;
                ig[(c + 2) * CS + k] = ph.z - ps.z + d2;
                ig[(c + 3) * CS + k] = ph.w - ps.w + d3;
                AG[(c + 0) * CS + k] = al.x + d0;
                AG[(c + 1) * CS + k] = al.y + d1;
                AG[(c + 2) * CS + k] = al.z + d2;
                AG[(c + 3) * CS + k] = al.w + d3;
            }
        }
        TEAM_BAR();

        // ---- g = relu(Wg @ ig); softmax over k; weighted sum ----
        ull acc[8];
        gemm64(acc, sWgT + 4 * og, ig + 4 * kg);
#pragma unroll
        for (int i = 0; i < 4; ++i) {
            float g0 = fmaxf(f2lo(acc[2*i]),   0.f);
            float g1 = fmaxf(f2hi(acc[2*i]),   0.f);
            float g2 = fmaxf(f2lo(acc[2*i+1]), 0.f);
            float g3 = fmaxf(f2hi(acc[2*i+1]), 0.f);
            float m = fmaxf(fmaxf(g0, g1), fmaxf(g2, g3));
            m = fmaxf(m, __shfl_xor_sync(0xffffffffu, m, 1));
            m = fmaxf(m, __shfl_xor_sync(0xffffffffu, m, 2));
            float e0 = __expf(g0 - m), e1 = __expf(g1 - m);
            float e2 = __expf(g2 - m), e3 = __expf(g3 - m);
            float s = (e0 + e1) + (e2 + e3);
            float4 a = *(const float4*)&AG[(4 * og + i) * CS + 4 * kg];
            float num = fmaf(e0, a.x, fmaf(e1, a.y, fmaf(e2, a.z, e3 * a.w)));
            s   += __shfl_xor_sync(0xffffffffu, s, 1);
            num += __shfl_xor_sync(0xffffffffu, num, 1);
            s   += __shfl_xor_sync(0xffffffffu, s, 2);
            num += __shfl_xor_sync(0xffffffffu, num, 2);
            if (kg == 0)
                out[((size_t)b * CO + 4 * og + i) * NPTS + n] = num / s;
        }
        TEAM_BAR();
    }
}

// ---------------------------------------------------------------------------
#define FUSED_SMEM ((4288 + PPT * TA) * sizeof(float))
extern "C" void kernel_launch(void* const* d_in, const int* in_sizes, int n_in,
                              void* d_out, int out_size) {
    const float* features = (const float*)d_in[0];
    const float* coords   = (const float*)d_in[1];
    const float* w_lin    = (const float*)d_in[2];
    const float* w_theta1 = (const float*)d_in[3];
    const float* w_theta2 = (const float*)d_in[4];
    const float* w_gamma1 = (const float*)d_in[5];
    const float* w_gamma2 = (const float*)d_in[6];
    float* out = (float*)d_out;

    static bool attr_set = false;
    if (!attr_set) {
        cudaFuncSetAttribute(fused_kernel, cudaFuncAttributeMaxDynamicSharedMemorySize,
                             FUSED_SMEM);
        cudaFuncSetAttribute(knn_kernel, cudaFuncAttributeMaxDynamicSharedMemorySize,
                             KNN_SMEM);
        attr_set = true;
    }

    knn_kernel<<<dim3(NPTS / QB, BATCH), QB, KNN_SMEM>>>(coords);
    wprep<<<16, 256>>>(w_theta1, w_theta2, w_gamma1, w_gamma2);
    feat3_kernel<<<dim3(NPTS / 128, BATCH), 128>>>(features, w_lin);
    fused_kernel<<<2048, 256, FUSED_SMEM>>>(coords, out);
}

// round 8
// speedup vs baseline: 1.8303x; 1.1340x over previous
#include <cuda_runtime.h>
#include <cstdint>

#define BATCH 4
#define NPTS  8192
#define KNN   16
#define CIN   64
#define CO    64
#define F3    192
#define CS    20
#define PPT   4
#define NQ    (BATCH * NPTS)
#define QB    128                 // queries per knn block (= threads)
#define TPAIRS 1024               // pairs per smem tile (2048 cands)
#define CHUNKS 2
#define CPC    (NPTS / CHUNKS)    // 4096 candidates per chunk
#define TILES_PER_CHUNK (CPC / (2 * TPAIRS))   // 2

typedef unsigned long long ull;
typedef unsigned int uint;

__device__ int   g_idx[NQ * KNN];
__device__ float g_feat3[(size_t)NQ * F3];
__device__ float g_pd[CHUNKS * NQ * KNN];
__device__ int   g_pi[CHUNKS * NQ * KNN];
__device__ float g_WgT[CO * CO];   // [c][o] = (w_gamma2 @ w_gamma1)^T
__device__ float g_WtT[3 * CO];    // [c3][o] = (w_theta2 @ w_theta1)^T

// ---------------------------------------------------------------------------
// packed f32x2 helpers
// ---------------------------------------------------------------------------
__device__ __forceinline__ ull pack2(float f) {
    ull r; uint u = __float_as_uint(f);
    asm("mov.b64 %0, {%1, %1};" : "=l"(r) : "r"(u));
    return r;
}
__device__ __forceinline__ ull packpair(float lo, float hi) {
    ull r;
    asm("mov.b64 %0, {%1, %2};" : "=l"(r) : "r"(__float_as_uint(lo)), "r"(__float_as_uint(hi)));
    return r;
}
__device__ __forceinline__ void fma2(ull& acc, ull a, ull b) {
    asm("fma.rn.f32x2 %0, %1, %2, %0;" : "+l"(acc) : "l"(a), "l"(b));
}
__device__ __forceinline__ float f2lo(ull v) { return __uint_as_float((uint)v); }
__device__ __forceinline__ float f2hi(ull v) { return __uint_as_float((uint)(v >> 32)); }

// ---------------------------------------------------------------------------
__device__ __forceinline__ void insert16(float d, int id, float bd[KNN], int bi[KNN]) {
#pragma unroll
    for (int t = 0; t < KNN; ++t) {
        bool p = d < bd[t];
        float td = bd[t]; int ti = bi[t];
        bd[t] = p ? d : bd[t];
        bi[t] = p ? id : bi[t];
        d  = p ? td : d;
        id = p ? ti : id;
    }
}

// ---------------------------------------------------------------------------
// KNN state + windowed scan helper
// ---------------------------------------------------------------------------
struct KS {
    float bd[KNN]; int bi[KNN];
    float thr; int cnt;
};

__device__ __forceinline__ void scan_window(const ull* __restrict__ s_pt,
                                            int j0, int j1, int ibase,
                                            ull nx, ull ny, ull nz,
                                            KS& st, float* s_bd, int* s_bi, int tid) {
#pragma unroll 4
    for (int jp = j0; jp < j1; ++jp) {
        ulonglong2 p01 = *(const ulonglong2*)(s_pt + (size_t)jp * 4);
        ulonglong2 p23 = *(const ulonglong2*)(s_pt + (size_t)jp * 4 + 2);
        ull d2 = p23.y;
        fma2(d2, nz, p23.x);
        fma2(d2, ny, p01.y);
        fma2(d2, nx, p01.x);
        float d0 = f2lo(d2), d1 = f2hi(d2);
        if (fminf(d0, d1) < st.thr) {
            const int i0 = ibase + 2 * jp;
            if (d0 < st.thr) {
                if (st.cnt < KNN) { s_bd[st.cnt * QB + tid] = d0; s_bi[st.cnt * QB + tid] = i0; st.cnt++; }
                else { insert16(d0, i0, st.bd, st.bi); st.thr = st.bd[KNN - 1]; }
            }
            if (d1 < st.thr) {
                if (st.cnt < KNN) { s_bd[st.cnt * QB + tid] = d1; s_bi[st.cnt * QB + tid] = i0 + 1; st.cnt++; }
                else { insert16(d1, i0 + 1, st.bd, st.bi); st.thr = st.bd[KNN - 1]; }
            }
        }
    }
    for (int u = 0; u < st.cnt; ++u) {
        float d = s_bd[u * QB + tid];
        if (d < st.thr) {
            insert16(d, s_bi[u * QB + tid], st.bd, st.bi);
            st.thr = st.bd[KNN - 1];
        }
    }
    st.cnt = 0;
}

// ---------------------------------------------------------------------------
// Kernel 1: partial KNN over one 4096-candidate chunk, 2 sequential tiles.
// key = |m|^2 - 2 q.m  (query norm dropped; order-preserving)
// ---------------------------------------------------------------------------
__global__ void __launch_bounds__(QB) knn_part(const float* __restrict__ coords) {
    extern __shared__ ull s_dyn[];
    ull*   s_pt = s_dyn;                          // [TPAIRS][4]  32KB
    float* s_bd = (float*)(s_dyn + TPAIRS * 4);   // [KNN][QB]    8KB
    int*   s_bi = (int*)(s_bd + KNN * QB);        // [KNN][QB]    8KB

    const int tid = threadIdx.x;
    const int b = blockIdx.y;
    const int chunk = blockIdx.z;
    const int q = blockIdx.x * QB + tid;
    const float* cb = coords + (size_t)b * 3 * NPTS;

    const ull nx = pack2(-2.f * cb[q]);
    const ull ny = pack2(-2.f * cb[NPTS + q]);
    const ull nz = pack2(-2.f * cb[2 * NPTS + q]);

    KS st;
#pragma unroll
    for (int j = 0; j < KNN; ++j) { st.bd[j] = 3.4e38f; st.bi[j] = 0; }
    st.thr = 3.4e38f; st.cnt = 0;

    for (int tile = 0; tile < TILES_PER_CHUNK; ++tile) {
        const int cbase = chunk * CPC + tile * 2 * TPAIRS;
        __syncthreads();
        for (int jp = tid; jp < TPAIRS; jp += QB) {
            float2 x = *(const float2*)(cb + cbase + 2 * jp);
            float2 y = *(const float2*)(cb + NPTS + cbase + 2 * jp);
            float2 z = *(const float2*)(cb + 2 * NPTS + cbase + 2 * jp);
            float w0 = fmaf(z.x, z.x, fmaf(y.x, y.x, x.x * x.x));
            float w1 = fmaf(z.y, z.y, fmaf(y.y, y.y, x.y * x.y));
            ull* p = s_pt + (size_t)jp * 4;
            p[0] = packpair(x.x, x.y);
            p[1] = packpair(y.x, y.y);
            p[2] = packpair(z.x, z.y);
            p[3] = packpair(w0, w1);
        }
        __syncthreads();

        if (tile == 0) {
            // geometric windows: (0,8),(8,16),(16,32),...,(512,1024) pairs
            for (int w = 0; w < 8; ++w) {
                const int j0 = (w == 0) ? 0 : (4 << w);
                const int j1 = 8 << w;
                scan_window(s_pt, j0, j1, cbase, nx, ny, nz, st, s_bd, s_bi, tid);
            }
        } else {
            // whole tile as one window (expected hits ~16*ln2 ~= 11 <= CAP)
            scan_window(s_pt, 0, TPAIRS, cbase, nx, ny, nz, st, s_bd, s_bi, tid);
        }
    }

    const int qg = b * NPTS + q;
    float* pd = g_pd + ((size_t)chunk * NQ + qg) * KNN;
    int*   pi = g_pi + ((size_t)chunk * NQ + qg) * KNN;
#pragma unroll
    for (int j = 0; j < KNN; ++j) { pd[j] = st.bd[j]; pi[j] = st.bi[j]; }
}
#define KNN_SMEM (TPAIRS * 4 * sizeof(ull) + KNN * QB * (sizeof(float) + sizeof(int)))

// ---------------------------------------------------------------------------
// Kernel 1b: merge 2 sorted partial lists -> final top-16
// ---------------------------------------------------------------------------
__global__ void __launch_bounds__(256) knn_merge() {
    const int qg = blockIdx.x * 256 + threadIdx.x;
    float bd[KNN]; int bi[KNN];

    const float4* p0d = (const float4*)(g_pd + (size_t)qg * KNN);
    const int4*   p0i = (const int4*)(g_pi + (size_t)qg * KNN);
#pragma unroll
    for (int v = 0; v < 4; ++v) {
        float4 d4 = p0d[v]; int4 i4 = p0i[v];
        bd[4*v] = d4.x; bd[4*v+1] = d4.y; bd[4*v+2] = d4.z; bd[4*v+3] = d4.w;
        bi[4*v] = i4.x; bi[4*v+1] = i4.y; bi[4*v+2] = i4.z; bi[4*v+3] = i4.w;
    }
    float bd15 = bd[KNN - 1];

    for (int c = 1; c < CHUNKS; ++c) {
        const float* pd = g_pd + ((size_t)c * NQ + qg) * KNN;
        const int*   pi = g_pi + ((size_t)c * NQ + qg) * KNN;
        for (int j = 0; j < KNN; ++j) {
            float d = pd[j];
            if (d >= bd15) break;      // sorted ascending
            insert16(d, pi[j], bd, bi);
            bd15 = bd[KNN - 1];
        }
    }
    int* op = g_idx + (size_t)qg * KNN;
#pragma unroll
    for (int j = 0; j < KNN; ++j) op[j] = bi[j];
}

// ---------------------------------------------------------------------------
// Kernel W: precombine weights (no ReLU between pairs -> linear fold)
// ---------------------------------------------------------------------------
__global__ void __launch_bounds__(256) wprep(const float* __restrict__ w_theta1,
                                             const float* __restrict__ w_theta2,
                                             const float* __restrict__ w_gamma1,
                                             const float* __restrict__ w_gamma2) {
    __shared__ float s1[4096], s2[4096];
    const int t = threadIdx.x;
    for (int i = t; i < 4096; i += 256) { s1[i] = w_gamma1[i]; s2[i] = w_gamma2[i]; }
    __syncthreads();
    {
        int i = blockIdx.x * 256 + t;
        int c = i >> 6, o = i & 63;
        float a = 0.f;
#pragma unroll 16
        for (int m = 0; m < 64; ++m) a = fmaf(s2[o * 64 + m], s1[m * 64 + c], a);
        g_WgT[c * 64 + o] = a;
    }
    if (blockIdx.x == 0 && t < 192) {
        int c3 = t / 64, o = t % 64;
        float a = 0.f;
#pragma unroll 16
        for (int m = 0; m < 64; ++m) a = fmaf(w_theta2[o * 64 + m], w_theta1[m * 3 + c3], a);
        g_WtT[c3 * 64 + o] = a;
    }
}

// ---------------------------------------------------------------------------
// Kernel 2: feat3[b,n,o] = sum_c w_lin[o,c] * features[b,c,n]
// ---------------------------------------------------------------------------
__global__ void __launch_bounds__(128) feat3_kernel(const float* __restrict__ features,
                                                    const float* __restrict__ w_lin) {
    __shared__ float sw[F3 * CIN];
    for (int i = threadIdx.x; i < F3 * CIN; i += 128) sw[i] = w_lin[i];

    const int b = blockIdx.y;
    const int n = blockIdx.x * 128 + threadIdx.x;

    float f[CIN];
    const float* fb = features + (size_t)b * CIN * NPTS + n;
#pragma unroll
    for (int c = 0; c < CIN; ++c) f[c] = fb[(size_t)c * NPTS];
    __syncthreads();

    float* outp = g_feat3 + ((size_t)b * NPTS + n) * F3;
    const float4* sw4 = (const float4*)sw;
#pragma unroll 1
    for (int og = 0; og < F3 / 4; ++og) {
        float a0 = 0.f, a1 = 0.f, a2 = 0.f, a3 = 0.f;
#pragma unroll
        for (int c4 = 0; c4 < CIN / 4; ++c4) {
            float4 w0 = sw4[(og * 4 + 0) * 16 + c4];
            float4 w1 = sw4[(og * 4 + 1) * 16 + c4];
            float4 w2 = sw4[(og * 4 + 2) * 16 + c4];
            float4 w3 = sw4[(og * 4 + 3) * 16 + c4];
            int c = c4 * 4;
            a0 = fmaf(w0.x, f[c], fmaf(w0.y, f[c+1], fmaf(w0.z, f[c+2], fmaf(w0.w, f[c+3], a0))));
            a1 = fmaf(w1.x, f[c], fmaf(w1.y, f[c+1], fmaf(w1.z, f[c+2], fmaf(w1.w, f[c+3], a1))));
            a2 = fmaf(w2.x, f[c], fmaf(w2.y, f[c+1], fmaf(w2.z, f[c+2], fmaf(w2.w, f[c+3], a2))));
            a3 = fmaf(w3.x, f[c], fmaf(w3.y, f[c+1], fmaf(w3.z, f[c+2], fmaf(w3.w, f[c+3], a3))));
        }
        ((float4*)outp)[og] = make_float4(a0, a1, a2, a3);
    }
}

// ---------------------------------------------------------------------------
__device__ __forceinline__ void gemm64(ull acc[8], const float* __restrict__ wcolT,
                                       const float* __restrict__ vrow) {
#pragma unroll
    for (int p = 0; p < 8; ++p) acc[p] = 0ull;
#pragma unroll 16
    for (int c = 0; c < 64; ++c) {
        float4 w = *(const float4*)(wcolT + c * 64);
        double2 vv = *(const double2*)(vrow + c * CS);
        ull v0 = __double_as_longlong(vv.x);
        ull v1 = __double_as_longlong(vv.y);
        ull w0 = pack2(w.x), w1 = pack2(w.y), w2 = pack2(w.z), w3 = pack2(w.w);
        fma2(acc[0], w0, v0); fma2(acc[1], w0, v1);
        fma2(acc[2], w1, v0); fma2(acc[3], w1, v1);
        fma2(acc[4], w2, v0); fma2(acc[5], w2, v1);
        fma2(acc[6], w3, v0); fma2(acc[7], w3, v1);
    }
}

#define TEAM_BAR() asm volatile("bar.sync %0, 64;" :: "r"(barid) : "memory")

// ---------------------------------------------------------------------------
// Kernel 3: fused attention (round-4/7 proven version)
// ---------------------------------------------------------------------------
#define TA 2560
__global__ void __launch_bounds__(256) fused_kernel(const float* __restrict__ coords,
                                                    float* __restrict__ out) {
    extern __shared__ float sm[];
    float* sWgT = sm;            // 4096  [c][o]
    float* sWtT = sm + 4096;     // 192   [c3][o]

    const int tid = threadIdx.x;
    for (int i = tid; i < 4096; i += 256) sWgT[i] = g_WgT[i];
    if (tid < 192) sWtT[tid] = g_WtT[tid];
    __syncthreads();

    const int gq  = tid >> 6;
    const int t64 = tid & 63;
    const int og  = t64 >> 2;
    const int kg  = t64 & 3;
    const int k    = t64 & 15;
    const int half = t64 >> 4;
    const int barid = gq + 1;

    float* ig = sm + 4288 + gq * TA;   // [64][CS]
    float* AG = ig + 1280;             // [64][CS]

    for (int P = blockIdx.x * PPT + gq; P < NQ; P += gridDim.x * PPT) {
        const int b = P >> 13;
        const int n = P & (NPTS - 1);

        // ---- gather + delta + staging ----
        {
            int ik = g_idx[(size_t)P * KNN + k];
            const float* cb = coords + (size_t)b * 3 * NPTS;
            float rx = cb[n]            - cb[ik];
            float ry = cb[NPTS + n]     - cb[NPTS + ik];
            float rz = cb[2 * NPTS + n] - cb[2 * NPTS + ik];

            const float* fb = g_feat3 + (size_t)(b * NPTS + ik) * F3;
            const float* fq = g_feat3 + (size_t)P * F3;
#pragma unroll
            for (int c4 = 0; c4 < 4; ++c4) {
                int c = half * 16 + c4 * 4;
                float4 ph = *(const float4*)(fq + c);
                float4 ps = *(const float4*)(fb + 64 + c);
                float4 al = *(const float4*)(fb + 128 + c);
                float4 w0 = *(const float4*)(sWtT + c);
                float4 w1 = *(const float4*)(sWtT + 64 + c);
                float4 w2 = *(const float4*)(sWtT + 128 + c);
                float d0 = fmaxf(fmaf(w2.x, rz, fmaf(w1.x, ry, w0.x * rx)), 0.f);
                float d1 = fmaxf(fmaf(w2.y, rz, fmaf(w1.y, ry, w0.y * rx)), 0.f);
                float d2 = fmaxf(fmaf(w2.z, rz, fmaf(w1.z, ry, w0.z * rx)), 0.f);
                float d3 = fmaxf(fmaf(w2.w, rz, fmaf(w1.w, ry, w0.w * rx)), 0.f);
                ig[(c + 0) * CS + k] = ph.x - ps.x + d0;
                ig[(c + 1) * CS + k] = ph.y - ps.y + d1;
                ig[(c + 2) * CS + k] = ph.z - ps.z + d2;
                ig[(c + 3) * CS + k] = ph.w - ps.w + d3;
                AG[(c + 0) * CS + k] = al.x + d0;
                AG[(c + 1) * CS + k] = al.y + d1;
                AG[(c + 2) * CS + k] = al.z + d2;
                AG[(c + 3) * CS + k] = al.w + d3;
            }
        }
        TEAM_BAR();

        // ---- g = relu(Wg @ ig); softmax over k; weighted sum ----
        ull acc[8];
        gemm64(acc, sWgT + 4 * og, ig + 4 * kg);
#pragma unroll
        for (int i = 0; i < 4; ++i) {
            float g0 = fmaxf(f2lo(acc[2*i]),   0.f);
            float g1 = fmaxf(f2hi(acc[2*i]),   0.f);
            float g2 = fmaxf(f2lo(acc[2*i+1]), 0.f);
            float g3 = fmaxf(f2hi(acc[2*i+1]), 0.f);
            float m = fmaxf(fmaxf(g0, g1), fmaxf(g2, g3));
            m = fmaxf(m, __shfl_xor_sync(0xffffffffu, m, 1));
            m = fmaxf(m, __shfl_xor_sync(0xffffffffu, m, 2));
            float e0 = __expf(g0 - m), e1 = __expf(g1 - m);
            float e2 = __expf(g2 - m), e3 = __expf(g3 - m);
            float s = (e0 + e1) + (e2 + e3);
            float4 a = *(const float4*)&AG[(4 * og + i) * CS + 4 * kg];
            float num = fmaf(e0, a.x, fmaf(e1, a.y, fmaf(e2, a.z, e3 * a.w)));
            s   += __shfl_xor_sync(0xffffffffu, s, 1);
            num += __shfl_xor_sync(0xffffffffu, num, 1);
            s   += __shfl_xor_sync(0xffffffffu, s, 2);
            num += __shfl_xor_sync(0xffffffffu, num, 2);
            if (kg == 0)
                out[((size_t)b * CO + 4 * og + i) * NPTS + n] = num / s;
        }
        TEAM_BAR();
    }
}

// ---------------------------------------------------------------------------
#define FUSED_SMEM ((4288 + PPT * TA) * sizeof(float))
extern "C" void kernel_launch(void* const* d_in, const int* in_sizes, int n_in,
                              void* d_out, int out_size) {
    const float* features = (const float*)d_in[0];
    const float* coords   = (const float*)d_in[1];
    const float* w_lin    = (const float*)d_in[2];
    const float* w_theta1 = (const float*)d_in[3];
    const float* w_theta2 = (const float*)d_in[4];
    const float* w_gamma1 = (const float*)d_in[5];
    const float* w_gamma2 = (const float*)d_in[6];
    float* out = (float*)d_out;

    static bool attr_set = false;
    if (!attr_set) {
        cudaFuncSetAttribute(fused_kernel, cudaFuncAttributeMaxDynamicSharedMemorySize,
                             FUSED_SMEM);
        cudaFuncSetAttribute(knn_part, cudaFuncAttributeMaxDynamicSharedMemorySize,
                             KNN_SMEM);
        attr_set = true;
    }

    knn_part<<<dim3(NPTS / QB, BATCH, CHUNKS), QB, KNN_SMEM>>>(coords);
    wprep<<<16, 256>>>(w_theta1, w_theta2, w_gamma1, w_gamma2);
    feat3_kernel<<<dim3(NPTS / 128, BATCH), 128>>>(features, w_lin);
    knn_merge<<<NQ / 256, 256>>>();
    fused_kernel<<<2048, 256, FUSED_SMEM>>>(coords, out);
}